// round 1
// baseline (speedup 1.0000x reference)
#include <cuda_runtime.h>
#include <math.h>

#define Bb   2
#define Tt   2048
#define DIMc 1024
#define NHh  16
#define HDd  64
#define NTOK (Bb*Tt)

// Scratch (device globals — no runtime allocation allowed)
__device__ float g_qkv[(size_t)NTOK * 3 * DIMc];   // [tok][3*DIM]  q|k|v
__device__ float g_y[(size_t)NTOK * DIMc];         // attention output [tok][DIM]

// ---------------------------------------------------------------------------
// Generic fp32 GEMM: C[M,N] = A[M,K] * B[K,N], row-major, all dims % 64/16 == 0
// 64x64 tile, BK=16, 256 threads, 4x4 register blocking.
// ---------------------------------------------------------------------------
__global__ __launch_bounds__(256) void sgemm64x64(
    const float* __restrict__ A, const float* __restrict__ Bm,
    float* __restrict__ C, int M, int N, int K)
{
    __shared__ float As[16][68];   // A^T tile: As[k][m], pad 68 keeps 16B align + banks
    __shared__ float Bs[16][64];   // B tile:   Bs[k][n]

    const int tid = threadIdx.x;
    const int m0 = blockIdx.y * 64;
    const int n0 = blockIdx.x * 64;
    const int tr = tid >> 4;       // 0..15 (row group)
    const int tc = tid & 15;       // 0..15 (col group)
    const int arow = tid >> 2, alane = tid & 3;    // A loader: 64 rows x 4 float4
    const int brow = tid >> 4, blane = tid & 15;   // B loader: 16 rows x 16 float4

    float acc[4][4] = {};

    for (int k0 = 0; k0 < K; k0 += 16) {
        float4 av = *(const float4*)&A[(size_t)(m0 + arow) * K + k0 + alane * 4];
        float4 bv = *(const float4*)&Bm[(size_t)(k0 + brow) * N + n0 + blane * 4];
        As[alane * 4 + 0][arow] = av.x;
        As[alane * 4 + 1][arow] = av.y;
        As[alane * 4 + 2][arow] = av.z;
        As[alane * 4 + 3][arow] = av.w;
        *(float4*)&Bs[brow][blane * 4] = bv;
        __syncthreads();

        #pragma unroll
        for (int k = 0; k < 16; k++) {
            float a[4], b[4];
            #pragma unroll
            for (int i = 0; i < 4; i++) a[i] = As[k][tr * 4 + i];
            #pragma unroll
            for (int j = 0; j < 4; j++) b[j] = Bs[k][tc * 4 + j];
            #pragma unroll
            for (int i = 0; i < 4; i++)
                #pragma unroll
                for (int j = 0; j < 4; j++)
                    acc[i][j] = fmaf(a[i], b[j], acc[i][j]);
        }
        __syncthreads();
    }

    #pragma unroll
    for (int i = 0; i < 4; i++) {
        float4 st = make_float4(acc[i][0], acc[i][1], acc[i][2], acc[i][3]);
        *(float4*)&C[(size_t)(m0 + tr * 4 + i) * N + n0 + tc * 4] = st;
    }
}

// ---------------------------------------------------------------------------
// RoPE applied in place to the Q and K segments of g_qkv.
// out[2i]   = x[2i]*cos - x[2i+1]*sin
// out[2i+1] = x[2i+1]*cos + x[2i]*sin   (cos/sin repeated pairwise)
// grid: NTOK blocks x 1024 threads; thread j handles one even/odd pair.
// ---------------------------------------------------------------------------
__global__ __launch_bounds__(1024) void rope_kernel(
    const float* __restrict__ sin_, const float* __restrict__ cos_)
{
    const int tok = blockIdx.x;
    const int t = tok & (Tt - 1);
    const int j = threadIdx.x;          // 0..1023
    const int seg = j >> 9;             // 0 = q, 1 = k
    const int p = j & 511;              // pair index within segment
    float* base = g_qkv + (size_t)tok * 3 * DIMc + seg * DIMc;
    const int d = p * 2;
    const int dh = d & (HDd - 1);
    const float c = cos_[t * HDd + dh];
    const float s = sin_[t * HDd + dh];
    float2 v = *(float2*)&base[d];
    float2 r = make_float2(v.x * c - v.y * s, v.y * c + v.x * s);
    *(float2*)&base[d] = r;
}

// ---------------------------------------------------------------------------
// Flash attention, fp32, causal. BQ = BKV = 64, 256 threads, 4x4 per thread.
// Smem: Qs[64][64], KS[64][64] (K^T, later aliased by S/P), Vs[64][64],
//       row_m/row_l/row_c[64].  Total 49,920 B (dynamic).
// ---------------------------------------------------------------------------
#define FLASH_SMEM ((3 * 64 * 64 + 3 * 64) * 4)

__global__ __launch_bounds__(256) void flash_kernel(float* __restrict__ Y)
{
    extern __shared__ float sm[];
    float* Qs   = sm;                  // [64][64]  Q (pre-scaled)
    float* KS   = sm + 4096;           // [64][64]  K^T, then S/P (row-major [q][kv])
    float* Vs   = sm + 8192;           // [64][64]  V [kv][d]
    float* row_m = sm + 12288;
    float* row_l = row_m + 64;
    float* row_c = row_l + 64;

    const int qt = blockIdx.x;         // q tile (32)
    const int h  = blockIdx.y;         // head (16)
    const int b  = blockIdx.z;         // batch (2)
    const int tid = threadIdx.x;
    const int tr = tid >> 4;           // 0..15
    const int tc = tid & 15;           // 0..15
    const int lrow = tid >> 2, llane = tid & 3;

    const int tok0 = b * Tt + qt * 64;
    const float* qbase = g_qkv + (size_t)tok0 * 3 * DIMc + h * HDd;

    // Load Q (scaled by 1/sqrt(64))
    #pragma unroll
    for (int cc = 0; cc < 4; cc++) {
        const int col = cc * 16 + llane * 4;
        float4 v = *(const float4*)(qbase + (size_t)lrow * 3 * DIMc + col);
        v.x *= 0.125f; v.y *= 0.125f; v.z *= 0.125f; v.w *= 0.125f;
        *(float4*)&Qs[lrow * 64 + col] = v;
    }
    if (tid < 64) { row_m[tid] = -INFINITY; row_l[tid] = 0.0f; }

    float o[4][4] = {};

    for (int kt = 0; kt <= qt; kt++) {
        const int ktok0 = b * Tt + kt * 64;
        const float* kbase = g_qkv + (size_t)ktok0 * 3 * DIMc + DIMc + h * HDd;
        const float* vbase = kbase + DIMc;

        __syncthreads();   // previous tile's reads of KS/Vs done; Qs/row init visible

        // Load K^T into KS (KS[d][kv]) and V into Vs (Vs[kv][d])
        #pragma unroll
        for (int cc = 0; cc < 4; cc++) {
            const int col = cc * 16 + llane * 4;
            float4 kv4 = *(const float4*)(kbase + (size_t)lrow * 3 * DIMc + col);
            KS[(col + 0) * 64 + lrow] = kv4.x;
            KS[(col + 1) * 64 + lrow] = kv4.y;
            KS[(col + 2) * 64 + lrow] = kv4.z;
            KS[(col + 3) * 64 + lrow] = kv4.w;
            float4 vv = *(const float4*)(vbase + (size_t)lrow * 3 * DIMc + col);
            *(float4*)&Vs[lrow * 64 + col] = vv;
        }
        __syncthreads();

        // S = Q * K^T  (Q already scaled)
        float s_[4][4] = {};
        #pragma unroll
        for (int d0 = 0; d0 < 64; d0 += 4) {
            float a[4][4], bk[4][4];
            #pragma unroll
            for (int i = 0; i < 4; i++) {
                float4 t = *(const float4*)&Qs[(tr * 4 + i) * 64 + d0];
                a[i][0] = t.x; a[i][1] = t.y; a[i][2] = t.z; a[i][3] = t.w;
            }
            #pragma unroll
            for (int dd = 0; dd < 4; dd++) {
                float4 t = *(const float4*)&KS[(d0 + dd) * 64 + tc * 4];
                bk[dd][0] = t.x; bk[dd][1] = t.y; bk[dd][2] = t.z; bk[dd][3] = t.w;
            }
            #pragma unroll
            for (int i = 0; i < 4; i++)
                #pragma unroll
                for (int j = 0; j < 4; j++)
                    s_[i][j] += a[i][0] * bk[0][j] + a[i][1] * bk[1][j]
                              + a[i][2] * bk[2][j] + a[i][3] * bk[3][j];
        }

        // Causal mask on the diagonal tile
        if (kt == qt) {
            #pragma unroll
            for (int i = 0; i < 4; i++)
                #pragma unroll
                for (int j = 0; j < 4; j++)
                    if ((tc * 4 + j) > (tr * 4 + i)) s_[i][j] = -INFINITY;
        }

        __syncthreads();   // all K^T reads done before overwriting KS with S

        #pragma unroll
        for (int i = 0; i < 4; i++) {
            float4 st = make_float4(s_[i][0], s_[i][1], s_[i][2], s_[i][3]);
            *(float4*)&KS[(tr * 4 + i) * 64 + tc * 4] = st;
        }
        __syncthreads();

        // Online softmax (one thread per q row; bank-rotated scan)
        if (tid < 64) {
            const int q = tid;
            const float m_old = row_m[q];
            float mx = m_old;
            #pragma unroll 8
            for (int kk = 0; kk < 64; kk++) {
                const int kv = (kk + q) & 63;
                mx = fmaxf(mx, KS[q * 64 + kv]);
            }
            const float corr = __expf(m_old - mx);
            float l = row_l[q] * corr;
            #pragma unroll 8
            for (int kk = 0; kk < 64; kk++) {
                const int kv = (kk + q) & 63;
                const float p = __expf(KS[q * 64 + kv] - mx);
                KS[q * 64 + kv] = p;
                l += p;
            }
            row_m[q] = mx; row_l[q] = l; row_c[q] = corr;
        }
        __syncthreads();

        // Rescale O and accumulate O += P * V
        float ci[4];
        #pragma unroll
        for (int i = 0; i < 4; i++) ci[i] = row_c[tr * 4 + i];
        #pragma unroll
        for (int i = 0; i < 4; i++)
            #pragma unroll
            for (int j = 0; j < 4; j++) o[i][j] *= ci[i];

        #pragma unroll
        for (int kv0 = 0; kv0 < 64; kv0 += 4) {
            float p[4][4], v4[4][4];
            #pragma unroll
            for (int i = 0; i < 4; i++) {
                float4 t = *(const float4*)&KS[(tr * 4 + i) * 64 + kv0];
                p[i][0] = t.x; p[i][1] = t.y; p[i][2] = t.z; p[i][3] = t.w;
            }
            #pragma unroll
            for (int kk = 0; kk < 4; kk++) {
                float4 t = *(const float4*)&Vs[(kv0 + kk) * 64 + tc * 4];
                v4[kk][0] = t.x; v4[kk][1] = t.y; v4[kk][2] = t.z; v4[kk][3] = t.w;
            }
            #pragma unroll
            for (int i = 0; i < 4; i++)
                #pragma unroll
                for (int j = 0; j < 4; j++)
                    o[i][j] += p[i][0] * v4[0][j] + p[i][1] * v4[1][j]
                             + p[i][2] * v4[2][j] + p[i][3] * v4[3][j];
        }
    }

    // Epilogue: divide by l, write Y[tok][h*64 + d]
    #pragma unroll
    for (int i = 0; i < 4; i++) {
        const float li = 1.0f / row_l[tr * 4 + i];
        float4 st = make_float4(o[i][0] * li, o[i][1] * li, o[i][2] * li, o[i][3] * li);
        *(float4*)&Y[(size_t)(tok0 + tr * 4 + i) * DIMc + h * HDd + tc * 4] = st;
    }
}

// ---------------------------------------------------------------------------
extern "C" void kernel_launch(void* const* d_in, const int* in_sizes, int n_in,
                              void* d_out, int out_size)
{
    const float* x      = (const float*)d_in[0];
    const float* sin_   = (const float*)d_in[1];
    const float* cos_   = (const float*)d_in[2];
    const float* W_qkv  = (const float*)d_in[3];
    const float* W_proj = (const float*)d_in[4];
    float* out = (float*)d_out;

    void* pqkv = nullptr;
    void* py   = nullptr;
    cudaGetSymbolAddress(&pqkv, g_qkv);
    cudaGetSymbolAddress(&py, g_y);

    cudaFuncSetAttribute(flash_kernel,
                         cudaFuncAttributeMaxDynamicSharedMemorySize, FLASH_SMEM);

    // 1) QKV = x @ W_qkv    (4096 x 3072 x 1024)
    sgemm64x64<<<dim3(3 * DIMc / 64, NTOK / 64), 256>>>(
        x, W_qkv, (float*)pqkv, NTOK, 3 * DIMc, DIMc);

    // 2) RoPE on q, k (in place)
    rope_kernel<<<NTOK, 1024>>>(sin_, cos_);

    // 3) Causal flash attention -> g_y
    flash_kernel<<<dim3(Tt / 64, NHh, Bb), 256, FLASH_SMEM>>>((float*)py);

    // 4) out = Y @ W_proj   (4096 x 1024 x 1024)
    sgemm64x64<<<dim3(DIMc / 64, NTOK / 64), 256>>>(
        (const float*)py, W_proj, out, NTOK, DIMc, DIMc);
}

// round 6
// speedup vs baseline: 1.0582x; 1.0582x over previous
#include <cuda_runtime.h>
#include <math.h>
#include <stdint.h>

#define Bb   2
#define Tt   2048
#define DIMc 1024
#define NHh  16
#define HDd  64
#define NTOK (Bb*Tt)

// Scratch (device globals — no runtime allocation allowed)
__device__ float g_qkv[(size_t)NTOK * 3 * DIMc];     // [tok][3*DIM]  q|k|v
__device__ float g_y[(size_t)NTOK * DIMc];           // attention output [tok][DIM]
__device__ float g_wqkv_t[(size_t)3 * DIMc * DIMc];  // W_qkv^T [3*DIM][DIM]
__device__ float g_wproj_t[(size_t)DIMc * DIMc];     // W_proj^T [DIM][DIM]

// ===========================================================================
// Helpers
// ===========================================================================
__device__ __forceinline__ uint32_t smem_u32(const void* p) {
    uint32_t a;
    asm("{ .reg .u64 t; cvta.to.shared.u64 t, %1; cvt.u32.u64 %0, t; }" : "=r"(a) : "l"(p));
    return a;
}
__device__ __forceinline__ void cp_async16(uint32_t dst, const void* src) {
    asm volatile("cp.async.cg.shared.global [%0], [%1], 16;" :: "r"(dst), "l"(src));
}
#define CP_COMMIT()  asm volatile("cp.async.commit_group;")
#define CP_WAIT1()   asm volatile("cp.async.wait_group 1;" ::: "memory")
#define CP_WAIT0()   asm volatile("cp.async.wait_group 0;" ::: "memory")

// Round f32 -> tf32 (round-to-nearest-even into the 10-bit-mantissa format)
__device__ __forceinline__ uint32_t f2tf32(float f) {
    uint32_t r;
    asm("cvt.rna.tf32.f32 %0, %1;" : "=r"(r) : "f"(f));
    return r;
}

// tf32 mma: D = A(16x8, row) * B(8x8, col) + D
__device__ __forceinline__ void mma_tf32(float* d, const uint32_t* a, const uint32_t* b) {
    asm volatile(
        "mma.sync.aligned.m16n8k8.row.col.f32.tf32.tf32.f32 "
        "{%0,%1,%2,%3}, {%4,%5,%6,%7}, {%8,%9}, {%0,%1,%2,%3};"
        : "+f"(d[0]), "+f"(d[1]), "+f"(d[2]), "+f"(d[3])
        : "r"(a[0]), "r"(a[1]), "r"(a[2]), "r"(a[3]), "r"(b[0]), "r"(b[1]));
}

// ===========================================================================
// Weight transpose: Wt[n][k] = W[k][n]
// ===========================================================================
__global__ __launch_bounds__(256) void transpose_k(
    const float* __restrict__ W, float* __restrict__ Wt, int K, int N)
{
    __shared__ float t[32][33];
    const int n0 = blockIdx.x * 32, k0 = blockIdx.y * 32;
    const int x = threadIdx.x, y = threadIdx.y;
    #pragma unroll
    for (int i = y; i < 32; i += 8)
        t[i][x] = W[(size_t)(k0 + i) * N + n0 + x];
    __syncthreads();
    #pragma unroll
    for (int i = y; i < 32; i += 8)
        Wt[(size_t)(n0 + i) * K + k0 + x] = t[x][i];
}

// ===========================================================================
// 3xTF32 GEMM: C[M,N] = A[M,K] * Bt[N,K]^T  at ~fp32 accuracy.
// CTA tile 128x128, BK=32, 8 warps (2m x 4n), warp tile 64x32.
// Smem layout (crosswise-4): elem(m,k) at (k/4)*512 + m*4 + (k%4)
//   -> cp.async 16B chunks contiguous; fragment LDS conflict-free.
// Each operand fragment is split hi/lo; acc += ahi*bhi + ahi*blo + alo*bhi.
// ===========================================================================
#define GEMM_SMEM (2 * 8192 * 4)   // 2 stages x (A 4096 + B 4096 floats) = 64 KB

__global__ __launch_bounds__(256) void gemm_mma(
    const float* __restrict__ A, const float* __restrict__ Bt,
    float* __restrict__ C, int M, int N, int K)
{
    extern __shared__ float sm[];

    const int tid  = threadIdx.x;
    const int lane = tid & 31;
    const int wid  = tid >> 5;
    const int wm   = wid >> 2;         // 0..1  (64-row slab)
    const int wn   = wid & 3;          // 0..3  (32-col slab)
    const int r    = lane >> 2;        // 0..7
    const int c    = lane & 3;         // 0..3
    const int m0 = blockIdx.y * 128, n0 = blockIdx.x * 128;
    const int NK = K >> 5;

    float acc[4][4][4] = {};           // [m-tile][n-tile][c-regs]

    auto load_stage = [&](int kt, int s) {
        const int k0 = kt * 32;
        float* a_s = sm + s * 8192;
        float* b_s = a_s + 4096;
        #pragma unroll
        for (int i = 0; i < 4; i++) {
            const int idx = tid + i * 256;     // 0..1023
            const int m = idx >> 3, q = idx & 7;
            cp_async16(smem_u32(a_s + q * 512 + m * 4),
                       &A[(size_t)(m0 + m) * K + k0 + q * 4]);
            cp_async16(smem_u32(b_s + q * 512 + m * 4),
                       &Bt[(size_t)(n0 + m) * K + k0 + q * 4]);
        }
    };

    load_stage(0, 0);
    CP_COMMIT();

    for (int kt = 0; kt < NK; kt++) {
        const int s = kt & 1;
        if (kt + 1 < NK) {
            load_stage(kt + 1, s ^ 1);
            CP_COMMIT();
            CP_WAIT1();
        } else {
            CP_WAIT0();
        }
        __syncthreads();

        const float* a_s = sm + s * 8192;
        const float* b_s = a_s + 4096;

        #pragma unroll
        for (int ks = 0; ks < 4; ks++) {       // k = 8*ks .. 8*ks+7
            uint32_t ahi[4][4], alo[4][4], bhi[4][2], blo[4][2];
            #pragma unroll
            for (int i = 0; i < 4; i++) {
                const float* p = a_s + (2 * ks) * 512 + (wm * 64 + i * 16 + r) * 4 + c;
                float v0 = p[0], v1 = p[32], v2 = p[512], v3 = p[544];
                ahi[i][0] = f2tf32(v0); alo[i][0] = f2tf32(v0 - __uint_as_float(ahi[i][0]));
                ahi[i][1] = f2tf32(v1); alo[i][1] = f2tf32(v1 - __uint_as_float(ahi[i][1]));
                ahi[i][2] = f2tf32(v2); alo[i][2] = f2tf32(v2 - __uint_as_float(ahi[i][2]));
                ahi[i][3] = f2tf32(v3); alo[i][3] = f2tf32(v3 - __uint_as_float(ahi[i][3]));
            }
            #pragma unroll
            for (int j = 0; j < 4; j++) {
                const float* p = b_s + (2 * ks) * 512 + (wn * 32 + j * 8 + r) * 4 + c;
                float v0 = p[0], v1 = p[512];
                bhi[j][0] = f2tf32(v0); blo[j][0] = f2tf32(v0 - __uint_as_float(bhi[j][0]));
                bhi[j][1] = f2tf32(v1); blo[j][1] = f2tf32(v1 - __uint_as_float(bhi[j][1]));
            }
            #pragma unroll
            for (int i = 0; i < 4; i++)
                #pragma unroll
                for (int j = 0; j < 4; j++) {
                    mma_tf32(acc[i][j], alo[i], bhi[j]);
                    mma_tf32(acc[i][j], ahi[i], blo[j]);
                    mma_tf32(acc[i][j], ahi[i], bhi[j]);
                }
        }
        __syncthreads();
    }

    // Epilogue: c0,c1 -> (row, 2c..2c+1); c2,c3 -> (row+8, ...)
    #pragma unroll
    for (int i = 0; i < 4; i++) {
        const int row = m0 + wm * 64 + i * 16 + r;
        #pragma unroll
        for (int j = 0; j < 4; j++) {
            const int col = n0 + wn * 32 + j * 8 + 2 * c;
            *(float2*)&C[(size_t)row * N + col] =
                make_float2(acc[i][j][0], acc[i][j][1]);
            *(float2*)&C[(size_t)(row + 8) * N + col] =
                make_float2(acc[i][j][2], acc[i][j][3]);
        }
    }
}

// ===========================================================================
// RoPE (in place on q, k segments of g_qkv)
// ===========================================================================
__global__ __launch_bounds__(1024) void rope_kernel(
    const float* __restrict__ sin_, const float* __restrict__ cos_)
{
    const int tok = blockIdx.x;
    const int t = tok & (Tt - 1);
    const int j = threadIdx.x;
    const int seg = j >> 9;
    const int p = j & 511;
    float* base = g_qkv + (size_t)tok * 3 * DIMc + seg * DIMc;
    const int d = p * 2;
    const int dh = d & (HDd - 1);
    const float c = cos_[t * HDd + dh];
    const float s = sin_[t * HDd + dh];
    float2 v = *(float2*)&base[d];
    float2 r = make_float2(v.x * c - v.y * s, v.y * c + v.x * s);
    *(float2*)&base[d] = r;
}

// ===========================================================================
// Flash attention, fp32, causal. BQ=BKV=64, 256 threads, 4x4 per thread.
// ===========================================================================
#define FLASH_SMEM ((3 * 64 * 64 + 3 * 64) * 4)

__global__ __launch_bounds__(256) void flash_kernel(float* __restrict__ Y)
{
    extern __shared__ float fsm[];
    float* Qs    = fsm;
    float* KS    = fsm + 4096;
    float* Vs    = fsm + 8192;
    float* row_m = fsm + 12288;
    float* row_l = row_m + 64;
    float* row_c = row_l + 64;

    const int qt = blockIdx.x;
    const int h  = blockIdx.y;
    const int b  = blockIdx.z;
    const int tid = threadIdx.x;
    const int tr = tid >> 4;
    const int tc = tid & 15;
    const int lrow = tid >> 2, llane = tid & 3;

    const int tok0 = b * Tt + qt * 64;
    const float* qbase = g_qkv + (size_t)tok0 * 3 * DIMc + h * HDd;

    #pragma unroll
    for (int cc = 0; cc < 4; cc++) {
        const int col = cc * 16 + llane * 4;
        float4 v = *(const float4*)(qbase + (size_t)lrow * 3 * DIMc + col);
        v.x *= 0.125f; v.y *= 0.125f; v.z *= 0.125f; v.w *= 0.125f;
        *(float4*)&Qs[lrow * 64 + col] = v;
    }
    if (tid < 64) { row_m[tid] = -INFINITY; row_l[tid] = 0.0f; }

    float o[4][4] = {};

    for (int kt = 0; kt <= qt; kt++) {
        const int ktok0 = b * Tt + kt * 64;
        const float* kbase = g_qkv + (size_t)ktok0 * 3 * DIMc + DIMc + h * HDd;
        const float* vbase = kbase + DIMc;

        __syncthreads();

        #pragma unroll
        for (int cc = 0; cc < 4; cc++) {
            const int col = cc * 16 + llane * 4;
            float4 kv4 = *(const float4*)(kbase + (size_t)lrow * 3 * DIMc + col);
            KS[(col + 0) * 64 + lrow] = kv4.x;
            KS[(col + 1) * 64 + lrow] = kv4.y;
            KS[(col + 2) * 64 + lrow] = kv4.z;
            KS[(col + 3) * 64 + lrow] = kv4.w;
            float4 vv = *(const float4*)(vbase + (size_t)lrow * 3 * DIMc + col);
            *(float4*)&Vs[lrow * 64 + col] = vv;
        }
        __syncthreads();

        // S = Q * K^T
        float s_[4][4] = {};
        #pragma unroll
        for (int d0 = 0; d0 < 64; d0 += 4) {
            float a[4][4], bk[4][4];
            #pragma unroll
            for (int i = 0; i < 4; i++) {
                float4 t = *(const float4*)&Qs[(tr * 4 + i) * 64 + d0];
                a[i][0] = t.x; a[i][1] = t.y; a[i][2] = t.z; a[i][3] = t.w;
            }
            #pragma unroll
            for (int dd = 0; dd < 4; dd++) {
                float4 t = *(const float4*)&KS[(d0 + dd) * 64 + tc * 4];
                bk[dd][0] = t.x; bk[dd][1] = t.y; bk[dd][2] = t.z; bk[dd][3] = t.w;
            }
            #pragma unroll
            for (int i = 0; i < 4; i++)
                #pragma unroll
                for (int j = 0; j < 4; j++)
                    s_[i][j] += a[i][0] * bk[0][j] + a[i][1] * bk[1][j]
                              + a[i][2] * bk[2][j] + a[i][3] * bk[3][j];
        }

        if (kt == qt) {
            #pragma unroll
            for (int i = 0; i < 4; i++)
                #pragma unroll
                for (int j = 0; j < 4; j++)
                    if ((tc * 4 + j) > (tr * 4 + i)) s_[i][j] = -INFINITY;
        }

        __syncthreads();

        #pragma unroll
        for (int i = 0; i < 4; i++) {
            float4 st = make_float4(s_[i][0], s_[i][1], s_[i][2], s_[i][3]);
            *(float4*)&KS[(tr * 4 + i) * 64 + tc * 4] = st;
        }
        __syncthreads();

        // Parallel online softmax: 4 threads per row (quarter-row each)
        {
            const int q = tid >> 2;
            const int quad = tid & 3;
            float* row = &KS[q * 64 + quad * 16];
            const float m_old = row_m[q];
            float4 v0 = *(float4*)(row + 0);
            float4 v1 = *(float4*)(row + 4);
            float4 v2 = *(float4*)(row + 8);
            float4 v3 = *(float4*)(row + 12);
            float mx = fmaxf(fmaxf(fmaxf(v0.x, v0.y), fmaxf(v0.z, v0.w)),
                             fmaxf(fmaxf(v1.x, v1.y), fmaxf(v1.z, v1.w)));
            mx = fmaxf(mx, fmaxf(fmaxf(fmaxf(v2.x, v2.y), fmaxf(v2.z, v2.w)),
                                 fmaxf(fmaxf(v3.x, v3.y), fmaxf(v3.z, v3.w))));
            mx = fmaxf(mx, __shfl_xor_sync(0xffffffffu, mx, 1));
            mx = fmaxf(mx, __shfl_xor_sync(0xffffffffu, mx, 2));
            mx = fmaxf(mx, m_old);
            v0.x = __expf(v0.x - mx); v0.y = __expf(v0.y - mx);
            v0.z = __expf(v0.z - mx); v0.w = __expf(v0.w - mx);
            v1.x = __expf(v1.x - mx); v1.y = __expf(v1.y - mx);
            v1.z = __expf(v1.z - mx); v1.w = __expf(v1.w - mx);
            v2.x = __expf(v2.x - mx); v2.y = __expf(v2.y - mx);
            v2.z = __expf(v2.z - mx); v2.w = __expf(v2.w - mx);
            v3.x = __expf(v3.x - mx); v3.y = __expf(v3.y - mx);
            v3.z = __expf(v3.z - mx); v3.w = __expf(v3.w - mx);
            float l = (v0.x + v0.y + v0.z + v0.w) + (v1.x + v1.y + v1.z + v1.w)
                    + (v2.x + v2.y + v2.z + v2.w) + (v3.x + v3.y + v3.z + v3.w);
            *(float4*)(row + 0)  = v0;
            *(float4*)(row + 4)  = v1;
            *(float4*)(row + 8)  = v2;
            *(float4*)(row + 12) = v3;
            l += __shfl_xor_sync(0xffffffffu, l, 1);
            l += __shfl_xor_sync(0xffffffffu, l, 2);
            if (quad == 0) {
                const float corr = __expf(m_old - mx);
                row_m[q] = mx;
                row_l[q] = row_l[q] * corr + l;
                row_c[q] = corr;
            }
        }
        __syncthreads();

        // Rescale O, accumulate O += P * V
        float ci[4];
        #pragma unroll
        for (int i = 0; i < 4; i++) ci[i] = row_c[tr * 4 + i];
        #pragma unroll
        for (int i = 0; i < 4; i++)
            #pragma unroll
            for (int j = 0; j < 4; j++) o[i][j] *= ci[i];

        #pragma unroll
        for (int kv0 = 0; kv0 < 64; kv0 += 4) {
            float p[4][4], v4[4][4];
            #pragma unroll
            for (int i = 0; i < 4; i++) {
                float4 t = *(const float4*)&KS[(tr * 4 + i) * 64 + kv0];
                p[i][0] = t.x; p[i][1] = t.y; p[i][2] = t.z; p[i][3] = t.w;
            }
            #pragma unroll
            for (int kk = 0; kk < 4; kk++) {
                float4 t = *(const float4*)&Vs[(kv0 + kk) * 64 + tc * 4];
                v4[kk][0] = t.x; v4[kk][1] = t.y; v4[kk][2] = t.z; v4[kk][3] = t.w;
            }
            #pragma unroll
            for (int i = 0; i < 4; i++)
                #pragma unroll
                for (int j = 0; j < 4; j++)
                    o[i][j] += p[i][0] * v4[0][j] + p[i][1] * v4[1][j]
                             + p[i][2] * v4[2][j] + p[i][3] * v4[3][j];
        }
    }

    #pragma unroll
    for (int i = 0; i < 4; i++) {
        const float li = 1.0f / row_l[tr * 4 + i];
        float4 st = make_float4(o[i][0] * li, o[i][1] * li, o[i][2] * li, o[i][3] * li);
        *(float4*)&Y[(size_t)(tok0 + tr * 4 + i) * DIMc + h * HDd + tc * 4] = st;
    }
}

// ===========================================================================
extern "C" void kernel_launch(void* const* d_in, const int* in_sizes, int n_in,
                              void* d_out, int out_size)
{
    const float* x      = (const float*)d_in[0];
    const float* sin_   = (const float*)d_in[1];
    const float* cos_   = (const float*)d_in[2];
    const float* W_qkv  = (const float*)d_in[3];
    const float* W_proj = (const float*)d_in[4];
    float* out = (float*)d_out;

    void *pqkv = nullptr, *py = nullptr, *pwq = nullptr, *pwp = nullptr;
    cudaGetSymbolAddress(&pqkv, g_qkv);
    cudaGetSymbolAddress(&py, g_y);
    cudaGetSymbolAddress(&pwq, g_wqkv_t);
    cudaGetSymbolAddress(&pwp, g_wproj_t);

    cudaFuncSetAttribute(gemm_mma, cudaFuncAttributeMaxDynamicSharedMemorySize, GEMM_SMEM);
    cudaFuncSetAttribute(flash_kernel, cudaFuncAttributeMaxDynamicSharedMemorySize, FLASH_SMEM);

    // 0) Transpose weights -> [N][K] for the col-major mma B operand
    transpose_k<<<dim3(3 * DIMc / 32, DIMc / 32), dim3(32, 8)>>>(W_qkv, (float*)pwq, DIMc, 3 * DIMc);
    transpose_k<<<dim3(DIMc / 32, DIMc / 32), dim3(32, 8)>>>(W_proj, (float*)pwp, DIMc, DIMc);

    // 1) QKV = x @ W_qkv  (3xTF32 mma.sync)
    gemm_mma<<<dim3(3 * DIMc / 128, NTOK / 128), 256, GEMM_SMEM>>>(
        x, (const float*)pwq, (float*)pqkv, NTOK, 3 * DIMc, DIMc);

    // 2) RoPE on q, k
    rope_kernel<<<NTOK, 1024>>>(sin_, cos_);

    // 3) Causal flash attention
    flash_kernel<<<dim3(Tt / 64, NHh, Bb), 256, FLASH_SMEM>>>((float*)py);

    // 4) out = Y @ W_proj  (3xTF32 mma.sync)
    gemm_mma<<<dim3(DIMc / 128, NTOK / 128), 256, GEMM_SMEM>>>(
        (const float*)py, (const float*)pwp, out, NTOK, DIMc, DIMc);
}